// round 13
// baseline (speedup 1.0000x reference)
#include <cuda_runtime.h>
#include <cuda_bf16.h>
#include <cuda_fp16.h>
#include <cstdint>

// Problem constants
#define B_   16
#define SQ_  128
#define SV_  128
#define DQ_  512
#define DV_  512
#define U_   256

// ---------------------------------------------------------------------------
// Scratch (__device__ globals — no allocation APIs allowed)
// ---------------------------------------------------------------------------
__device__ float g_s1[B_ * SQ_ * U_];      // [2048][256]
__device__ float g_s2[B_ * SV_ * U_];      // [2048][256]
__device__ float g_score[B_ * SQ_ * SV_];  // [16][128][128]

// Fragment-native packed operands for the mma.sync GEMMs.
__device__ uint4 g_Ahp[2][128 * 32 * 32];
__device__ uint4 g_Alp[2][128 * 32 * 32];
__device__ uint4 g_Wp [2][ 32 * 32 * 32];

// ---------------------------------------------------------------------------
// Helpers
// ---------------------------------------------------------------------------
__device__ __forceinline__ uint32_t smem_u32(const void* p) {
    uint32_t a;
    asm("{ .reg .u64 t; cvta.to.shared.u64 t, %1; cvt.u32.u64 %0, t; }"
        : "=r"(a) : "l"(p));
    return a;
}
__device__ __forceinline__ void cp_async16(uint32_t s, const void* g) {
    asm volatile("cp.async.cg.shared.global [%0], [%1], 16;" :: "r"(s), "l"(g));
}
#define CP_COMMIT()  asm volatile("cp.async.commit_group;" ::: "memory")
#define CP_WAIT0()   asm volatile("cp.async.wait_group 0;" ::: "memory")

// mma.sync m16n8k16 bf16 (row.col), fp32 accumulate — base sm_80+ feature.
__device__ __forceinline__ void mma_bf16(float* d, const uint32_t* a,
                                         uint32_t b0, uint32_t b1) {
    asm volatile(
        "mma.sync.aligned.m16n8k16.row.col.f32.bf16.bf16.f32 "
        "{%0,%1,%2,%3}, {%4,%5,%6,%7}, {%8,%9}, {%0,%1,%2,%3};"
        : "+f"(d[0]), "+f"(d[1]), "+f"(d[2]), "+f"(d[3])
        : "r"(a[0]), "r"(a[1]), "r"(a[2]), "r"(a[3]), "r"(b0), "r"(b1));
}

// mma.sync m16n8k16 f16 inputs, fp32 accumulate.
__device__ __forceinline__ void mma_f16(float* d,
                                        uint32_t a0, uint32_t a1,
                                        uint32_t a2, uint32_t a3,
                                        uint32_t b0, uint32_t b1) {
    asm volatile(
        "mma.sync.aligned.m16n8k16.row.col.f32.f16.f16.f32 "
        "{%0,%1,%2,%3}, {%4,%5,%6,%7}, {%8,%9}, {%0,%1,%2,%3};"
        : "+f"(d[0]), "+f"(d[1]), "+f"(d[2]), "+f"(d[3])
        : "r"(a0), "r"(a1), "r"(a2), "r"(a3), "r"(b0), "r"(b1));
}

__device__ __forceinline__ uint32_t split_pack(float x0, float x1, uint32_t& lo_pack) {
    __nv_bfloat16 h0 = __float2bfloat16(x0);
    __nv_bfloat16 h1 = __float2bfloat16(x1);
    float r0 = x0 - __bfloat162float(h0);
    float r1 = x1 - __bfloat162float(h1);
    __nv_bfloat16 l0 = __float2bfloat16(r0);
    __nv_bfloat16 l1 = __float2bfloat16(r1);
    lo_pack = ((uint32_t)__bfloat16_as_ushort(l1) << 16) | __bfloat16_as_ushort(l0);
    return ((uint32_t)__bfloat16_as_ushort(h1) << 16) | __bfloat16_as_ushort(h0);
}

__device__ __forceinline__ uint32_t pack_h2(float x0, float x1) {
    __half2 h = __floats2half2_rn(x0, x1);
    return *(uint32_t*)&h;
}

// ---------------------------------------------------------------------------
// Kernel 0 (R9 version): fp32 -> bf16 (hi, lo) split into fragment layouts.
// grid (512, 4): y=0 query, y=1 values, y=2 W1, y=3 W2.
// ---------------------------------------------------------------------------
__global__ __launch_bounds__(256) void convert_kernel(
    const float* __restrict__ q, const float* __restrict__ v,
    const float* __restrict__ W1, const float* __restrict__ W2)
{
    const int z = blockIdx.y;
    const int j = blockIdx.x * 256 + threadIdx.x;

    if (z < 2) {
        const float* __restrict__ src = z ? v : q;       // [2048][512]
        const int rb   = j >> 10;            // 0..127
        const int ks   = (j >> 5) & 31;      // 0..31
        const int lane = j & 31;
        const int r0 = rb * 16 + (lane >> 2);
        const int k0 = ks * 16 + (lane & 3) * 2;

        float2 a00 = *(const float2*)&src[(size_t)r0 * 512 + k0];
        float2 a01 = *(const float2*)&src[(size_t)r0 * 512 + k0 + 8];
        float2 a10 = *(const float2*)&src[(size_t)(r0 + 8) * 512 + k0];
        float2 a11 = *(const float2*)&src[(size_t)(r0 + 8) * 512 + k0 + 8];

        uint4 hi, lo;
        hi.x = split_pack(a00.x, a00.y, lo.x);
        hi.y = split_pack(a10.x, a10.y, lo.y);
        hi.z = split_pack(a01.x, a01.y, lo.z);
        hi.w = split_pack(a11.x, a11.y, lo.w);
        g_Ahp[z][j] = hi;
        g_Alp[z][j] = lo;
    } else {
        if (j >= 32 * 32 * 32) return;
        const float* __restrict__ src = (z == 3) ? W2 : W1;  // [512][256]
        const int nb   = j >> 10;            // 0..31
        const int ks   = (j >> 5) & 31;
        const int lane = j & 31;
        const int n  = nb * 8 + (lane >> 2);
        const int k0 = ks * 16 + (lane & 3) * 2;

        float w00 = src[(size_t)k0 * 256 + n];
        float w01 = src[(size_t)(k0 + 1) * 256 + n];
        float w10 = src[(size_t)(k0 + 8) * 256 + n];
        float w11 = src[(size_t)(k0 + 9) * 256 + n];

        uint4 f;
        uint32_t l0, l1;
        f.x = split_pack(w00, w01, l0);
        f.y = split_pack(w10, w11, l1);
        f.z = l0;
        f.w = l1;
        g_Wp[z - 2][j] = f;
    }
}

// ---------------------------------------------------------------------------
// Kernel A (R9 version): tensor-core GEMM via mma.sync.
// ---------------------------------------------------------------------------
__global__ __launch_bounds__(256) void gemm_mma_kernel(
    const float* __restrict__ b1, const float* __restrict__ b2)
{
    const int tid  = threadIdx.x;
    const int wid  = tid >> 5;
    const int lane = tid & 31;
    const int g    = lane >> 2;
    const int tg   = lane & 3;

    const int z  = blockIdx.z;
    const int m0 = blockIdx.y * 128;
    const int n0 = blockIdx.x * 64;

    const uint4* __restrict__ Ah = g_Ahp[z];
    const uint4* __restrict__ Al = g_Alp[z];
    const uint4* __restrict__ Bp = g_Wp[z];
    float* __restrict__ C            = z ? g_s2 : g_s1;
    const float* __restrict__ bias   = z ? b2 : b1;

    const int warp_m = wid & 3;
    const int warp_n = wid >> 2;
    const int rb0 = (m0 >> 4) + warp_m * 2;
    const int nb0 = (n0 >> 3) + warp_n * 4;

    float acc[2][4][4];
#pragma unroll
    for (int mt = 0; mt < 2; mt++)
#pragma unroll
        for (int nt = 0; nt < 4; nt++)
#pragma unroll
            for (int c = 0; c < 4; c++) acc[mt][nt][c] = 0.f;

#pragma unroll 2
    for (int ks = 0; ks < 32; ks++) {
        uint4 AH[2], AL[2], Bf[4];
#pragma unroll
        for (int mt = 0; mt < 2; mt++) {
            AH[mt] = Ah[((rb0 + mt) * 32 + ks) * 32 + lane];
            AL[mt] = Al[((rb0 + mt) * 32 + ks) * 32 + lane];
        }
#pragma unroll
        for (int nt = 0; nt < 4; nt++)
            Bf[nt] = Bp[((nb0 + nt) * 32 + ks) * 32 + lane];

#pragma unroll
        for (int mt = 0; mt < 2; mt++)
#pragma unroll
            for (int nt = 0; nt < 4; nt++) {
                mma_bf16(acc[mt][nt], (const uint32_t*)&AH[mt], Bf[nt].x, Bf[nt].y);
                mma_bf16(acc[mt][nt], (const uint32_t*)&AH[mt], Bf[nt].z, Bf[nt].w);
                mma_bf16(acc[mt][nt], (const uint32_t*)&AL[mt], Bf[nt].x, Bf[nt].y);
            }
    }

#pragma unroll
    for (int mt = 0; mt < 2; mt++) {
        const int row = m0 + warp_m * 32 + mt * 16 + g;
#pragma unroll
        for (int nt = 0; nt < 4; nt++) {
            const int col = n0 + warp_n * 32 + nt * 8 + tg * 2;
            const float2 bb = *(const float2*)&bias[col];
            float2 o0, o1;
            o0.x = acc[mt][nt][0] + bb.x;
            o0.y = acc[mt][nt][1] + bb.y;
            o1.x = acc[mt][nt][2] + bb.x;
            o1.y = acc[mt][nt][3] + bb.y;
            *(float2*)&C[(size_t)row * U_ + col]       = o0;
            *(float2*)&C[(size_t)(row + 8) * U_ + col] = o1;
        }
    }
}

// ---------------------------------------------------------------------------
// Kernel B: score via tanh.approx.f16x2 feeding mma.sync directly.
// No half->float cvt, no FFMA in the reduction: A-fragment = tanh values
// (f16), B-fragment = Vw (f16, all n-columns identical), fp32 accum in D.
// Block: 32q x 32v tile, 8 warps; warp owns 4 q rows x 32 v = 8 mma tiles
// (tile m: q pair (m>>2)*2, v block (m&3)*8). k loop: 16 chunks of u=16.
// ---------------------------------------------------------------------------
__global__ __launch_bounds__(256) void score_kernel(
    const float* __restrict__ Vw, const float* __restrict__ Vb)
{
    __shared__ uint32_t sS1[32][132];   // [row][u-pair], stride 132 (bank-spread)
    __shared__ uint32_t sS2[32][132];
    __shared__ uint32_t sVw[128];       // Vw as 128 f16x2 pairs

    const int tid = threadIdx.x;
    const int b   = blockIdx.z;
    const int q0  = blockIdx.y * 32;
    const int v0  = blockIdx.x * 32;

    // Stage s1/s2 (fp32 -> f16x2 pairs) for all 256 u of this tile's rows.
#pragma unroll
    for (int it = 0; it < 8; it++) {
        const int idx = tid + it * 256;     // 0..2047 float4-units
        const int r   = idx >> 6;           // row 0..31
        const int c4  = idx & 63;           // float4 col (64 per row)
        float4 x1 = *(const float4*)&g_s1[((b * SQ_) + q0 + r) * U_ + (c4 << 2)];
        sS1[r][2 * c4]     = pack_h2(x1.x, x1.y);
        sS1[r][2 * c4 + 1] = pack_h2(x1.z, x1.w);
        float4 x2 = *(const float4*)&g_s2[((b * SV_) + v0 + r) * U_ + (c4 << 2)];
        sS2[r][2 * c4]     = pack_h2(x2.x, x2.y);
        sS2[r][2 * c4 + 1] = pack_h2(x2.z, x2.w);
    }
    if (tid < 128) sVw[tid] = pack_h2(Vw[2 * tid], Vw[2 * tid + 1]);
    __syncthreads();

    const int wid  = tid >> 5;
    const int lane = tid & 31;
    const int qq = wid * 4;          // warp's 4 q rows (local)
    const int tr = lane >> 2;        // 0..7 (mma row within tile)
    const int tc = lane & 3;         // 0..3 (mma k-group)

    float d[8][4];
#pragma unroll
    for (int m = 0; m < 8; m++)
#pragma unroll
        for (int c = 0; c < 4; c++) d[m][c] = 0.f;

#pragma unroll 4
    for (int kc = 0; kc < 16; kc++) {            // u chunk = kc*16 .. +15
        const uint32_t bf0 = sVw[kc * 8 + tc];       // B: k pairs 2tc, +1
        const uint32_t bf1 = sVw[kc * 8 + tc + 4];   //    k pairs 2tc+8, +9
        const int cp0 = kc * 8 + tc;                 // A u-pair (a0/a1)
        const int cp1 = cp0 + 4;                     // A u-pair (a2/a3)
#pragma unroll
        for (int m = 0; m < 8; m++) {
            const int ql = qq + ((m >> 2) << 1);     // q row for a0/a2
            const int vl = ((m & 3) << 3) + tr;      // v row (varies by lane)
            const uint32_t s2a = sS2[vl][cp0];
            const uint32_t s2b = sS2[vl][cp1];
            const uint32_t s1a = sS1[ql][cp0];
            const uint32_t s1b = sS1[ql + 1][cp0];
            const uint32_t s1c = sS1[ql][cp1];
            const uint32_t s1d = sS1[ql + 1][cp1];

            __half2 h0 = __hadd2(*(const __half2*)&s1a, *(const __half2*)&s2a);
            __half2 h1 = __hadd2(*(const __half2*)&s1b, *(const __half2*)&s2a);
            __half2 h2v = __hadd2(*(const __half2*)&s1c, *(const __half2*)&s2b);
            __half2 h3 = __hadd2(*(const __half2*)&s1d, *(const __half2*)&s2b);

            uint32_t a0, a1, a2, a3;
            asm("tanh.approx.f16x2 %0, %1;" : "=r"(a0) : "r"(*(uint32_t*)&h0));
            asm("tanh.approx.f16x2 %0, %1;" : "=r"(a1) : "r"(*(uint32_t*)&h1));
            asm("tanh.approx.f16x2 %0, %1;" : "=r"(a2) : "r"(*(uint32_t*)&h2v));
            asm("tanh.approx.f16x2 %0, %1;" : "=r"(a3) : "r"(*(uint32_t*)&h3));

            mma_f16(d[m], a0, a1, a2, a3, bf0, bf1);
        }
    }

    // D: row tr -> (q = ql, v = vl) in d[m][0]; row tr+8 -> q = ql+1 in d[m][2].
    // All n-columns identical, so every tc holds the value; write from tc==0.
    const float vb = Vb[0];
    if (tc == 0) {
#pragma unroll
        for (int m = 0; m < 8; m++) {
            const int ql = qq + ((m >> 2) << 1);
            const int vl = ((m & 3) << 3) + tr;
            g_score[((b * SQ_) + q0 + ql) * SV_ + v0 + vl]     = d[m][0] + vb;
            g_score[((b * SQ_) + q0 + ql + 1) * SV_ + v0 + vl] = d[m][2] + vb;
        }
    }
}

// ---------------------------------------------------------------------------
// Kernel C (R9 fused version): softmax + context.
// ---------------------------------------------------------------------------
__global__ __launch_bounds__(256) void ctx_kernel(
    const float* __restrict__ values,
    float* __restrict__ out_w,
    float* __restrict__ out_ctx)
{
    __shared__ float sW[32][128];
    __shared__ float sV[2][32 * 128];

    const int tid = threadIdx.x;
    const int b   = blockIdx.z;
    const int q0  = blockIdx.y * 32;
    const int d0  = blockIdx.x * 128;

    const float* __restrict__ vsrc = values + (size_t)b * SV_ * DV_ + d0;
    const uint32_t svb = smem_u32(&sV[0][0]);

#pragma unroll
    for (int k = 0; k < 4; k++) {
        const int idx = tid + k * 256;
        const int r   = idx >> 5;
        const int c4  = idx & 31;
        cp_async16(svb + (uint32_t)(r * 128 + c4 * 4) * 4,
                   vsrc + (size_t)r * DV_ + c4 * 4);
    }
    CP_COMMIT();

#pragma unroll
    for (int k = 0; k < 4; k++) {
        const int idx = tid + k * 256;
        const int r   = idx >> 5;
        const int c4  = idx & 31;
        float4 s = *(const float4*)&g_score[((b * SQ_) + q0 + r) * SV_ + (c4 << 2)];
        *(float4*)&sW[r][c4 << 2] = s;
    }
    __syncthreads();

    const int warp = tid >> 5;
    const int lane = tid & 31;
#pragma unroll
    for (int i = 0; i < 4; i++) {
        const int r = warp * 4 + i;
        float sc[4];
#pragma unroll
        for (int j = 0; j < 4; j++) sc[j] = sW[r][lane + 32 * j];
        float m = fmaxf(fmaxf(sc[0], sc[1]), fmaxf(sc[2], sc[3]));
#pragma unroll
        for (int o = 16; o > 0; o >>= 1)
            m = fmaxf(m, __shfl_xor_sync(0xFFFFFFFFu, m, o));
        float e[4], s = 0.f;
#pragma unroll
        for (int j = 0; j < 4; j++) { e[j] = __expf(sc[j] - m); s += e[j]; }
#pragma unroll
        for (int o = 16; o > 0; o >>= 1)
            s += __shfl_xor_sync(0xFFFFFFFFu, s, o);
        float inv = __fdividef(1.f, s);
#pragma unroll
        for (int j = 0; j < 4; j++) {
            float w = e[j] * inv;
            sW[r][lane + 32 * j] = w;
            if (blockIdx.x == 0)
                out_w[((b * SQ_) + q0 + r) * SV_ + lane + 32 * j] = w;
        }
    }

    const int dg = tid & 31;
    const int qg = tid >> 5;

    float4 acc[4];
#pragma unroll
    for (int i = 0; i < 4; i++) acc[i] = make_float4(0.f, 0.f, 0.f, 0.f);

#pragma unroll
    for (int c = 0; c < 4; c++) {
        CP_WAIT0();
        __syncthreads();

        if (c < 3) {
            const uint32_t nb = svb + (uint32_t)(((c + 1) & 1) * 32 * 128) * 4;
            const float* gsrc = vsrc + (size_t)(c + 1) * 32 * DV_;
#pragma unroll
            for (int k = 0; k < 4; k++) {
                const int idx = tid + k * 256;
                const int r   = idx >> 5;
                const int c4  = idx & 31;
                cp_async16(nb + (uint32_t)(r * 128 + c4 * 4) * 4,
                           gsrc + (size_t)r * DV_ + c4 * 4);
            }
            CP_COMMIT();
        }

        const float* sv = &sV[c & 1][0];
#pragma unroll
        for (int v = 0; v < 32; v++) {
            float4 vv = *(const float4*)&sv[v * 128 + (dg << 2)];
            const int gv = c * 32 + v;
#pragma unroll
            for (int i = 0; i < 4; i++) {
                float w = sW[qg * 4 + i][gv];
                acc[i].x = fmaf(w, vv.x, acc[i].x);
                acc[i].y = fmaf(w, vv.y, acc[i].y);
                acc[i].z = fmaf(w, vv.z, acc[i].z);
                acc[i].w = fmaf(w, vv.w, acc[i].w);
            }
        }
        __syncthreads();
    }

#pragma unroll
    for (int i = 0; i < 4; i++) {
        const int q = q0 + qg * 4 + i;
        *(float4*)&out_ctx[((size_t)(b * SQ_) + q) * DV_ + d0 + (dg << 2)] = acc[i];
    }
}

// ---------------------------------------------------------------------------
extern "C" void kernel_launch(void* const* d_in, const int* in_sizes, int n_in,
                              void* d_out, int out_size)
{
    const float* query  = (const float*)d_in[0];
    const float* values = (const float*)d_in[1];
    const float* W1     = (const float*)d_in[2];
    const float* b1     = (const float*)d_in[3];
    const float* W2     = (const float*)d_in[4];
    const float* b2     = (const float*)d_in[5];
    const float* Vw     = (const float*)d_in[6];
    const float* Vb     = (const float*)d_in[7];

    float* out_ctx = (float*)d_out;                      // [16,128,512]
    float* out_w   = out_ctx + B_ * SQ_ * DV_;           // [16,128,128,1]

    // fp32 -> bf16 hi/lo split into fragment-native packed layouts
    convert_kernel<<<dim3(512, 4), 256>>>(query, values, W1, W2);

    // tensor-core GEMMs: s1 = q@W1+b1, s2 = v@W2+b2
    gemm_mma_kernel<<<dim3(4, 16, 2), 256>>>(b1, b2);

    // score = reduce_u tanh(s1+s2)*Vw + Vb  (tanh.f16x2 -> mma.sync)
    score_kernel<<<dim3(SV_ / 32, SQ_ / 32, B_), 256>>>(Vw, Vb);

    // fused softmax + context
    ctx_kernel<<<dim3(4, 4, 16), 256>>>(values, out_w, out_ctx);
}

// round 14
// speedup vs baseline: 1.4450x; 1.4450x over previous
#include <cuda_runtime.h>
#include <cuda_bf16.h>
#include <cuda_fp16.h>
#include <cstdint>

// Problem constants
#define B_   16
#define SQ_  128
#define SV_  128
#define DQ_  512
#define DV_  512
#define U_   256

// ---------------------------------------------------------------------------
// Scratch (__device__ globals — no allocation APIs allowed)
// ---------------------------------------------------------------------------
__device__ float g_s1[B_ * SQ_ * U_];      // [2048][256]
__device__ float g_s2[B_ * SV_ * U_];      // [2048][256]
__device__ float g_score[B_ * SQ_ * SV_];  // [16][128][128]

// Fragment-native packed operands for the mma.sync GEMMs.
__device__ uint4 g_Ahp[2][128 * 32 * 32];
__device__ uint4 g_Alp[2][128 * 32 * 32];
__device__ uint4 g_Wp [2][ 32 * 32 * 32];
// values^T B-fragments for the ctx GEMM: [b][dblk(64)][ks(8)][lane(32)]
// uint4 {b0 hi, b1 hi, b0 lo, b1 lo} (f16 hi/lo split)
__device__ uint4 g_VTp[B_ * 64 * 8 * 32];

// ---------------------------------------------------------------------------
// Helpers
// ---------------------------------------------------------------------------
// mma.sync m16n8k16 bf16 (row.col), fp32 accumulate — base sm_80+ feature.
__device__ __forceinline__ void mma_bf16(float* d, const uint32_t* a,
                                         uint32_t b0, uint32_t b1) {
    asm volatile(
        "mma.sync.aligned.m16n8k16.row.col.f32.bf16.bf16.f32 "
        "{%0,%1,%2,%3}, {%4,%5,%6,%7}, {%8,%9}, {%0,%1,%2,%3};"
        : "+f"(d[0]), "+f"(d[1]), "+f"(d[2]), "+f"(d[3])
        : "r"(a[0]), "r"(a[1]), "r"(a[2]), "r"(a[3]), "r"(b0), "r"(b1));
}

// mma.sync m16n8k16 f16 inputs, fp32 accumulate.
__device__ __forceinline__ void mma_f16(float* d,
                                        uint32_t a0, uint32_t a1,
                                        uint32_t a2, uint32_t a3,
                                        uint32_t b0, uint32_t b1) {
    asm volatile(
        "mma.sync.aligned.m16n8k16.row.col.f32.f16.f16.f32 "
        "{%0,%1,%2,%3}, {%4,%5,%6,%7}, {%8,%9}, {%0,%1,%2,%3};"
        : "+f"(d[0]), "+f"(d[1]), "+f"(d[2]), "+f"(d[3])
        : "r"(a0), "r"(a1), "r"(a2), "r"(a3), "r"(b0), "r"(b1));
}

__device__ __forceinline__ uint32_t split_pack(float x0, float x1, uint32_t& lo_pack) {
    __nv_bfloat16 h0 = __float2bfloat16(x0);
    __nv_bfloat16 h1 = __float2bfloat16(x1);
    float r0 = x0 - __bfloat162float(h0);
    float r1 = x1 - __bfloat162float(h1);
    __nv_bfloat16 l0 = __float2bfloat16(r0);
    __nv_bfloat16 l1 = __float2bfloat16(r1);
    lo_pack = ((uint32_t)__bfloat16_as_ushort(l1) << 16) | __bfloat16_as_ushort(l0);
    return ((uint32_t)__bfloat16_as_ushort(h1) << 16) | __bfloat16_as_ushort(h0);
}

// f16 hi/lo split pack (for the ctx GEMM operands)
__device__ __forceinline__ uint32_t split_pack_h(float x0, float x1, uint32_t& lo_pack) {
    __half h0 = __float2half_rn(x0);
    __half h1 = __float2half_rn(x1);
    __half l0 = __float2half_rn(x0 - __half2float(h0));
    __half l1 = __float2half_rn(x1 - __half2float(h1));
    lo_pack = ((uint32_t)__half_as_ushort(l1) << 16) | __half_as_ushort(l0);
    return ((uint32_t)__half_as_ushort(h1) << 16) | __half_as_ushort(h0);
}

__device__ __forceinline__ uint32_t pack_h2(float x0, float x1) {
    __half2 h = __floats2half2_rn(x0, x1);
    return *(uint32_t*)&h;
}

// ---------------------------------------------------------------------------
// Kernel 0: fp32 -> packed fragment layouts.
// grid (1024, 5): y=0 query, y=1 values (A frags, bf16 hi/lo),
//                 y=2 W1, y=3 W2 (B frags, bf16 hi/lo),
//                 y=4 values^T (B frags, f16 hi/lo, per batch) for ctx GEMM.
// ---------------------------------------------------------------------------
__global__ __launch_bounds__(256) void convert_kernel(
    const float* __restrict__ q, const float* __restrict__ v,
    const float* __restrict__ W1, const float* __restrict__ W2)
{
    const int z = blockIdx.y;
    const int j = blockIdx.x * 256 + threadIdx.x;

    if (z < 2) {
        if (j >= 128 * 32 * 32) return;
        const float* __restrict__ src = z ? v : q;       // [2048][512]
        const int rb   = j >> 10;            // 0..127
        const int ks   = (j >> 5) & 31;      // 0..31
        const int lane = j & 31;
        const int r0 = rb * 16 + (lane >> 2);
        const int k0 = ks * 16 + (lane & 3) * 2;

        float2 a00 = *(const float2*)&src[(size_t)r0 * 512 + k0];
        float2 a01 = *(const float2*)&src[(size_t)r0 * 512 + k0 + 8];
        float2 a10 = *(const float2*)&src[(size_t)(r0 + 8) * 512 + k0];
        float2 a11 = *(const float2*)&src[(size_t)(r0 + 8) * 512 + k0 + 8];

        uint4 hi, lo;
        hi.x = split_pack(a00.x, a00.y, lo.x);
        hi.y = split_pack(a10.x, a10.y, lo.y);
        hi.z = split_pack(a01.x, a01.y, lo.z);
        hi.w = split_pack(a11.x, a11.y, lo.w);
        g_Ahp[z][j] = hi;
        g_Alp[z][j] = lo;
    } else if (z < 4) {
        if (j >= 32 * 32 * 32) return;
        const float* __restrict__ src = (z == 3) ? W2 : W1;  // [512][256]
        const int nb   = j >> 10;            // 0..31
        const int ks   = (j >> 5) & 31;
        const int lane = j & 31;
        const int n  = nb * 8 + (lane >> 2);
        const int k0 = ks * 16 + (lane & 3) * 2;

        float w00 = src[(size_t)k0 * 256 + n];
        float w01 = src[(size_t)(k0 + 1) * 256 + n];
        float w10 = src[(size_t)(k0 + 8) * 256 + n];
        float w11 = src[(size_t)(k0 + 9) * 256 + n];

        uint4 f;
        uint32_t l0, l1;
        f.x = split_pack(w00, w01, l0);
        f.y = split_pack(w10, w11, l1);
        f.z = l0;
        f.w = l1;
        g_Wp[z - 2][j] = f;
    } else {
        // values^T fragments: n = d (within-batch), k = v. Same B mapping as
        // z=2/3 (empirically verified by gemm), but f16 hi/lo, per batch.
        const int lane = j & 31;
        const int ks   = (j >> 5) & 7;       // v block of 16
        const int dblk = (j >> 8) & 63;      // d block of 8
        const int bb   = j >> 14;            // batch
        const int n  = dblk * 8 + (lane >> 2);        // d index
        const int k0 = ks * 16 + (lane & 3) * 2;      // v index

        const float* __restrict__ src = v + ((size_t)bb * 128 + k0) * 512 + n;
        float v00 = src[0];
        float v01 = src[512];
        float v10 = src[8 * 512];
        float v11 = src[9 * 512];

        uint4 f;
        f.x = split_pack_h(v00, v01, f.z);
        f.y = split_pack_h(v10, v11, f.w);
        g_VTp[j] = f;
    }
}

// ---------------------------------------------------------------------------
// Kernel A: tensor-core GEMM via mma.sync (bf16 hi/lo, fp32 accum).
// ---------------------------------------------------------------------------
__global__ __launch_bounds__(256) void gemm_mma_kernel(
    const float* __restrict__ b1, const float* __restrict__ b2)
{
    const int tid  = threadIdx.x;
    const int wid  = tid >> 5;
    const int lane = tid & 31;
    const int g    = lane >> 2;
    const int tg   = lane & 3;

    const int z  = blockIdx.z;
    const int m0 = blockIdx.y * 128;
    const int n0 = blockIdx.x * 64;

    const uint4* __restrict__ Ah = g_Ahp[z];
    const uint4* __restrict__ Al = g_Alp[z];
    const uint4* __restrict__ Bp = g_Wp[z];
    float* __restrict__ C            = z ? g_s2 : g_s1;
    const float* __restrict__ bias   = z ? b2 : b1;

    const int warp_m = wid & 3;
    const int warp_n = wid >> 2;
    const int rb0 = (m0 >> 4) + warp_m * 2;
    const int nb0 = (n0 >> 3) + warp_n * 4;

    float acc[2][4][4];
#pragma unroll
    for (int mt = 0; mt < 2; mt++)
#pragma unroll
        for (int nt = 0; nt < 4; nt++)
#pragma unroll
            for (int c = 0; c < 4; c++) acc[mt][nt][c] = 0.f;

#pragma unroll 2
    for (int ks = 0; ks < 32; ks++) {
        uint4 AH[2], AL[2], Bf[4];
#pragma unroll
        for (int mt = 0; mt < 2; mt++) {
            AH[mt] = Ah[((rb0 + mt) * 32 + ks) * 32 + lane];
            AL[mt] = Al[((rb0 + mt) * 32 + ks) * 32 + lane];
        }
#pragma unroll
        for (int nt = 0; nt < 4; nt++)
            Bf[nt] = Bp[((nb0 + nt) * 32 + ks) * 32 + lane];

#pragma unroll
        for (int mt = 0; mt < 2; mt++)
#pragma unroll
            for (int nt = 0; nt < 4; nt++) {
                mma_bf16(acc[mt][nt], (const uint32_t*)&AH[mt], Bf[nt].x, Bf[nt].y);
                mma_bf16(acc[mt][nt], (const uint32_t*)&AH[mt], Bf[nt].z, Bf[nt].w);
                mma_bf16(acc[mt][nt], (const uint32_t*)&AL[mt], Bf[nt].x, Bf[nt].y);
            }
    }

#pragma unroll
    for (int mt = 0; mt < 2; mt++) {
        const int row = m0 + warp_m * 32 + mt * 16 + g;
#pragma unroll
        for (int nt = 0; nt < 4; nt++) {
            const int col = n0 + warp_n * 32 + nt * 8 + tg * 2;
            const float2 bb = *(const float2*)&bias[col];
            float2 o0, o1;
            o0.x = acc[mt][nt][0] + bb.x;
            o0.y = acc[mt][nt][1] + bb.y;
            o1.x = acc[mt][nt][2] + bb.x;
            o1.y = acc[mt][nt][3] + bb.y;
            *(float2*)&C[(size_t)row * U_ + col]       = o0;
            *(float2*)&C[(size_t)(row + 8) * U_ + col] = o1;
        }
    }
}

// ---------------------------------------------------------------------------
// Kernel B (R13 version): score via tanh.approx.f16x2 feeding mma.sync.
// ---------------------------------------------------------------------------
__global__ __launch_bounds__(256) void score_kernel(
    const float* __restrict__ Vw, const float* __restrict__ Vb)
{
    __shared__ uint32_t sS1[32][132];
    __shared__ uint32_t sS2[32][132];
    __shared__ uint32_t sVw[128];

    const int tid = threadIdx.x;
    const int b   = blockIdx.z;
    const int q0  = blockIdx.y * 32;
    const int v0  = blockIdx.x * 32;

#pragma unroll
    for (int it = 0; it < 8; it++) {
        const int idx = tid + it * 256;
        const int r   = idx >> 6;
        const int c4  = idx & 63;
        float4 x1 = *(const float4*)&g_s1[((b * SQ_) + q0 + r) * U_ + (c4 << 2)];
        sS1[r][2 * c4]     = pack_h2(x1.x, x1.y);
        sS1[r][2 * c4 + 1] = pack_h2(x1.z, x1.w);
        float4 x2 = *(const float4*)&g_s2[((b * SV_) + v0 + r) * U_ + (c4 << 2)];
        sS2[r][2 * c4]     = pack_h2(x2.x, x2.y);
        sS2[r][2 * c4 + 1] = pack_h2(x2.z, x2.w);
    }
    if (tid < 128) sVw[tid] = pack_h2(Vw[2 * tid], Vw[2 * tid + 1]);
    __syncthreads();

    const int wid  = tid >> 5;
    const int lane = tid & 31;
    const int qq = wid * 4;
    const int tr = lane >> 2;
    const int tc = lane & 3;

    float d[8][4];
#pragma unroll
    for (int m = 0; m < 8; m++)
#pragma unroll
        for (int c = 0; c < 4; c++) d[m][c] = 0.f;

#pragma unroll 4
    for (int kc = 0; kc < 16; kc++) {
        const uint32_t bf0 = sVw[kc * 8 + tc];
        const uint32_t bf1 = sVw[kc * 8 + tc + 4];
        const int cp0 = kc * 8 + tc;
        const int cp1 = cp0 + 4;
#pragma unroll
        for (int m = 0; m < 8; m++) {
            const int ql = qq + ((m >> 2) << 1);
            const int vl = ((m & 3) << 3) + tr;
            const uint32_t s2a = sS2[vl][cp0];
            const uint32_t s2b = sS2[vl][cp1];
            const uint32_t s1a = sS1[ql][cp0];
            const uint32_t s1b = sS1[ql + 1][cp0];
            const uint32_t s1c = sS1[ql][cp1];
            const uint32_t s1d = sS1[ql + 1][cp1];

            __half2 h0 = __hadd2(*(const __half2*)&s1a, *(const __half2*)&s2a);
            __half2 h1 = __hadd2(*(const __half2*)&s1b, *(const __half2*)&s2a);
            __half2 h2v = __hadd2(*(const __half2*)&s1c, *(const __half2*)&s2b);
            __half2 h3 = __hadd2(*(const __half2*)&s1d, *(const __half2*)&s2b);

            uint32_t a0, a1, a2, a3;
            asm("tanh.approx.f16x2 %0, %1;" : "=r"(a0) : "r"(*(uint32_t*)&h0));
            asm("tanh.approx.f16x2 %0, %1;" : "=r"(a1) : "r"(*(uint32_t*)&h1));
            asm("tanh.approx.f16x2 %0, %1;" : "=r"(a2) : "r"(*(uint32_t*)&h2v));
            asm("tanh.approx.f16x2 %0, %1;" : "=r"(a3) : "r"(*(uint32_t*)&h3));

            mma_f16(d[m], a0, a1, a2, a3, bf0, bf1);
        }
    }

    const float vb = Vb[0];
    if (tc == 0) {
#pragma unroll
        for (int m = 0; m < 8; m++) {
            const int ql = qq + ((m >> 2) << 1);
            const int vl = ((m & 3) << 3) + tr;
            g_score[((b * SQ_) + q0 + ql) * SV_ + v0 + vl]     = d[m][0] + vb;
            g_score[((b * SQ_) + q0 + ql + 1) * SV_ + v0 + vl] = d[m][2] + vb;
        }
    }
}

// ---------------------------------------------------------------------------
// Kernel C: fused softmax + context GEMM via mma.sync (f16 hi/lo).
// Tile: 32 q x 128 d per block; grid (4 dtile, 4 qtile, 16 b) = 256 blocks.
// Phase 1: score tile -> softmax (fp32, exact; out_w written from d-tile 0).
// Phase 2: pack w -> f16 hi/lo fragments in smem; context = w @ values with
//          3-term mma (wh*vh + wh*vl + wl*vh), B fragments from g_VTp (L2).
// ---------------------------------------------------------------------------
__global__ __launch_bounds__(256) void ctx_kernel(
    float* __restrict__ out_w,
    float* __restrict__ out_ctx)
{
    __shared__ float    sW[32][128];
    __shared__ uint32_t sWh[32][66];   // w hi, f16x2 pairs over v
    __shared__ uint32_t sWl[32][66];   // w lo residuals

    const int tid = threadIdx.x;
    const int b   = blockIdx.z;
    const int q0  = blockIdx.y * 32;
    const int dt  = blockIdx.x;        // d tile: d0 = dt*128

    // Phase 1: load score tile + row softmax (fp32).
#pragma unroll
    for (int k = 0; k < 4; k++) {
        const int idx = tid + k * 256;
        const int r   = idx >> 5;
        const int c4  = idx & 31;
        float4 s = *(const float4*)&g_score[((b * SQ_) + q0 + r) * SV_ + (c4 << 2)];
        *(float4*)&sW[r][c4 << 2] = s;
    }
    __syncthreads();

    const int warp = tid >> 5;
    const int lane = tid & 31;
#pragma unroll
    for (int i = 0; i < 4; i++) {
        const int r = warp * 4 + i;
        float sc[4];
#pragma unroll
        for (int j = 0; j < 4; j++) sc[j] = sW[r][lane + 32 * j];
        float m = fmaxf(fmaxf(sc[0], sc[1]), fmaxf(sc[2], sc[3]));
#pragma unroll
        for (int o = 16; o > 0; o >>= 1)
            m = fmaxf(m, __shfl_xor_sync(0xFFFFFFFFu, m, o));
        float e[4], s = 0.f;
#pragma unroll
        for (int j = 0; j < 4; j++) { e[j] = __expf(sc[j] - m); s += e[j]; }
#pragma unroll
        for (int o = 16; o > 0; o >>= 1)
            s += __shfl_xor_sync(0xFFFFFFFFu, s, o);
        float inv = __fdividef(1.f, s);
#pragma unroll
        for (int j = 0; j < 4; j++) {
            float w = e[j] * inv;
            sW[r][lane + 32 * j] = w;
            if (dt == 0)
                out_w[((b * SQ_) + q0 + r) * SV_ + lane + 32 * j] = w;
        }
    }
    __syncthreads();

    // Pack w -> f16 hi/lo pair arrays (8 pairs per thread).
    {
        const int row = tid >> 3;
        const int p0  = (tid & 7) * 8;
#pragma unroll
        for (int p = 0; p < 8; p++) {
            const int pp = p0 + p;
            uint32_t l;
            sWh[row][pp] = split_pack_h(sW[row][2 * pp], sW[row][2 * pp + 1], l);
            sWl[row][pp] = l;
        }
    }
    __syncthreads();

    // Phase 2: context GEMM. Warp -> (mt = wid&1 of 2 m-tiles, ng = wid>>1 of
    // 4 n-groups x 4 dblks). k loop over 8 v-tiles of 16.
    const int tr = lane >> 2;
    const int tc = lane & 3;
    const int mt = warp & 1;
    const int ng = warp >> 1;
    const int r0 = mt * 16 + tr;

    float acc[4][4];
#pragma unroll
    for (int i = 0; i < 4; i++)
#pragma unroll
        for (int c = 0; c < 4; c++) acc[i][c] = 0.f;

    const uint4* __restrict__ Bp =
        g_VTp + (((size_t)b * 64 + (size_t)dt * 16) * 8) * 32;

#pragma unroll
    for (int k = 0; k < 8; k++) {
        const int cp = k * 8 + tc;
        const uint32_t ah0 = sWh[r0][cp];
        const uint32_t ah1 = sWh[r0 + 8][cp];
        const uint32_t ah2 = sWh[r0][cp + 4];
        const uint32_t ah3 = sWh[r0 + 8][cp + 4];
        const uint32_t al0 = sWl[r0][cp];
        const uint32_t al1 = sWl[r0 + 8][cp];
        const uint32_t al2 = sWl[r0][cp + 4];
        const uint32_t al3 = sWl[r0 + 8][cp + 4];
#pragma unroll
        for (int i = 0; i < 4; i++) {
            const int dblk = ng * 4 + i;          // local d-block (of 16)
            uint4 Bf = Bp[((size_t)dblk * 8 + k) * 32 + lane];
            mma_f16(acc[i], ah0, ah1, ah2, ah3, Bf.x, Bf.y);   // wh * vh
            mma_f16(acc[i], ah0, ah1, ah2, ah3, Bf.z, Bf.w);   // wh * vl
            mma_f16(acc[i], al0, al1, al2, al3, Bf.x, Bf.y);   // wl * vh
        }
    }

    // Epilogue: D rows q0+r0 (acc[.][0..1]) and q0+r0+8 (acc[.][2..3]),
    // cols d = dt*128 + dblk*8 + 2tc.
#pragma unroll
    for (int i = 0; i < 4; i++) {
        const int d  = dt * 128 + (ng * 4 + i) * 8 + tc * 2;
        const int qa = q0 + r0;
        float2 o0, o1;
        o0.x = acc[i][0]; o0.y = acc[i][1];
        o1.x = acc[i][2]; o1.y = acc[i][3];
        *(float2*)&out_ctx[((size_t)(b * SQ_) + qa) * DV_ + d]     = o0;
        *(float2*)&out_ctx[((size_t)(b * SQ_) + qa + 8) * DV_ + d] = o1;
    }
}

// ---------------------------------------------------------------------------
extern "C" void kernel_launch(void* const* d_in, const int* in_sizes, int n_in,
                              void* d_out, int out_size)
{
    const float* query  = (const float*)d_in[0];
    const float* values = (const float*)d_in[1];
    const float* W1     = (const float*)d_in[2];
    const float* b1     = (const float*)d_in[3];
    const float* W2     = (const float*)d_in[4];
    const float* b2     = (const float*)d_in[5];
    const float* Vw     = (const float*)d_in[6];
    const float* Vb     = (const float*)d_in[7];

    float* out_ctx = (float*)d_out;                      // [16,128,512]
    float* out_w   = out_ctx + B_ * SQ_ * DV_;           // [16,128,128,1]

    // fp32 -> packed fragment layouts (A/B for gemm, values^T for ctx)
    convert_kernel<<<dim3(1024, 5), 256>>>(query, values, W1, W2);

    // tensor-core GEMMs: s1 = q@W1+b1, s2 = v@W2+b2
    gemm_mma_kernel<<<dim3(4, 16, 2), 256>>>(b1, b2);

    // score = reduce_u tanh(s1+s2)*Vw + Vb  (tanh.f16x2 -> mma.sync)
    score_kernel<<<dim3(SV_ / 32, SQ_ / 32, B_), 256>>>(Vw, Vb);

    // fused softmax + context GEMM
    ctx_kernel<<<dim3(4, 4, 16), 256>>>(out_w, out_ctx);
}

// round 16
// speedup vs baseline: 1.5877x; 1.0988x over previous
#include <cuda_runtime.h>
#include <cuda_bf16.h>
#include <cuda_fp16.h>
#include <cstdint>

// Problem constants
#define B_   16
#define SQ_  128
#define SV_  128
#define DQ_  512
#define DV_  512
#define U_   256

// ---------------------------------------------------------------------------
// Scratch (__device__ globals — no allocation APIs allowed)
// ---------------------------------------------------------------------------
__device__ float g_s1[B_ * SQ_ * U_];      // [2048][256]
__device__ float g_s2[B_ * SV_ * U_];      // [2048][256]
__device__ float g_score[B_ * SQ_ * SV_];  // [16][128][128]

// Fragment-native packed operands for the mma.sync GEMMs.
__device__ uint4 g_Ahp[2][128 * 32 * 32];
__device__ uint4 g_Alp[2][128 * 32 * 32];
__device__ uint4 g_Wp [2][ 32 * 32 * 32];
// values^T B-fragments for the ctx GEMM: [b][dblk(64)][ks(8)][lane(32)]
// uint4 {b0 hi, b1 hi, b0 lo, b1 lo} (f16 hi/lo split)
__device__ uint4 g_VTp[B_ * 64 * 8 * 32];

// ---------------------------------------------------------------------------
// Helpers
// ---------------------------------------------------------------------------
__device__ __forceinline__ uint32_t smem_u32(const void* p) {
    uint32_t a;
    asm("{ .reg .u64 t; cvta.to.shared.u64 t, %1; cvt.u32.u64 %0, t; }"
        : "=r"(a) : "l"(p));
    return a;
}
__device__ __forceinline__ void cp_async16(uint32_t s, const void* g) {
    asm volatile("cp.async.cg.shared.global [%0], [%1], 16;" :: "r"(s), "l"(g));
}
#define CP_COMMIT()  asm volatile("cp.async.commit_group;" ::: "memory")
#define CP_WAIT0()   asm volatile("cp.async.wait_group 0;" ::: "memory")

// mma.sync m16n8k16 bf16 (row.col), fp32 accumulate — base sm_80+ feature.
__device__ __forceinline__ void mma_bf16(float* d, const uint32_t* a,
                                         uint32_t b0, uint32_t b1) {
    asm volatile(
        "mma.sync.aligned.m16n8k16.row.col.f32.bf16.bf16.f32 "
        "{%0,%1,%2,%3}, {%4,%5,%6,%7}, {%8,%9}, {%0,%1,%2,%3};"
        : "+f"(d[0]), "+f"(d[1]), "+f"(d[2]), "+f"(d[3])
        : "r"(a[0]), "r"(a[1]), "r"(a[2]), "r"(a[3]), "r"(b0), "r"(b1));
}

// mma.sync m16n8k16 f16 inputs, fp32 accumulate.
__device__ __forceinline__ void mma_f16(float* d,
                                        uint32_t a0, uint32_t a1,
                                        uint32_t a2, uint32_t a3,
                                        uint32_t b0, uint32_t b1) {
    asm volatile(
        "mma.sync.aligned.m16n8k16.row.col.f32.f16.f16.f32 "
        "{%0,%1,%2,%3}, {%4,%5,%6,%7}, {%8,%9}, {%0,%1,%2,%3};"
        : "+f"(d[0]), "+f"(d[1]), "+f"(d[2]), "+f"(d[3])
        : "r"(a0), "r"(a1), "r"(a2), "r"(a3), "r"(b0), "r"(b1));
}

__device__ __forceinline__ uint32_t split_pack(float x0, float x1, uint32_t& lo_pack) {
    __nv_bfloat16 h0 = __float2bfloat16(x0);
    __nv_bfloat16 h1 = __float2bfloat16(x1);
    float r0 = x0 - __bfloat162float(h0);
    float r1 = x1 - __bfloat162float(h1);
    __nv_bfloat16 l0 = __float2bfloat16(r0);
    __nv_bfloat16 l1 = __float2bfloat16(r1);
    lo_pack = ((uint32_t)__bfloat16_as_ushort(l1) << 16) | __bfloat16_as_ushort(l0);
    return ((uint32_t)__bfloat16_as_ushort(h1) << 16) | __bfloat16_as_ushort(h0);
}

// f16 hi/lo split pack (for the ctx GEMM operands)
__device__ __forceinline__ uint32_t split_pack_h(float x0, float x1, uint32_t& lo_pack) {
    __half h0 = __float2half_rn(x0);
    __half h1 = __float2half_rn(x1);
    __half l0 = __float2half_rn(x0 - __half2float(h0));
    __half l1 = __float2half_rn(x1 - __half2float(h1));
    lo_pack = ((uint32_t)__half_as_ushort(l1) << 16) | __half_as_ushort(l0);
    return ((uint32_t)__half_as_ushort(h1) << 16) | __half_as_ushort(h0);
}

__device__ __forceinline__ uint32_t pack_h2(float x0, float x1) {
    __half2 h = __floats2half2_rn(x0, x1);
    return *(uint32_t*)&h;
}

// ---------------------------------------------------------------------------
// Kernel 0 (R14 version): fp32 -> packed fragment layouts.
// grid (1024, 5): y=0 query, y=1 values (A frags), y=2 W1, y=3 W2 (B frags),
//                 y=4 values^T (B frags, f16 hi/lo, per batch) for ctx GEMM.
// ---------------------------------------------------------------------------
__global__ __launch_bounds__(256) void convert_kernel(
    const float* __restrict__ q, const float* __restrict__ v,
    const float* __restrict__ W1, const float* __restrict__ W2)
{
    const int z = blockIdx.y;
    const int j = blockIdx.x * 256 + threadIdx.x;

    if (z < 2) {
        if (j >= 128 * 32 * 32) return;
        const float* __restrict__ src = z ? v : q;       // [2048][512]
        const int rb   = j >> 10;            // 0..127
        const int ks   = (j >> 5) & 31;      // 0..31
        const int lane = j & 31;
        const int r0 = rb * 16 + (lane >> 2);
        const int k0 = ks * 16 + (lane & 3) * 2;

        float2 a00 = *(const float2*)&src[(size_t)r0 * 512 + k0];
        float2 a01 = *(const float2*)&src[(size_t)r0 * 512 + k0 + 8];
        float2 a10 = *(const float2*)&src[(size_t)(r0 + 8) * 512 + k0];
        float2 a11 = *(const float2*)&src[(size_t)(r0 + 8) * 512 + k0 + 8];

        uint4 hi, lo;
        hi.x = split_pack(a00.x, a00.y, lo.x);
        hi.y = split_pack(a10.x, a10.y, lo.y);
        hi.z = split_pack(a01.x, a01.y, lo.z);
        hi.w = split_pack(a11.x, a11.y, lo.w);
        g_Ahp[z][j] = hi;
        g_Alp[z][j] = lo;
    } else if (z < 4) {
        if (j >= 32 * 32 * 32) return;
        const float* __restrict__ src = (z == 3) ? W2 : W1;  // [512][256]
        const int nb   = j >> 10;            // 0..31
        const int ks   = (j >> 5) & 31;
        const int lane = j & 31;
        const int n  = nb * 8 + (lane >> 2);
        const int k0 = ks * 16 + (lane & 3) * 2;

        float w00 = src[(size_t)k0 * 256 + n];
        float w01 = src[(size_t)(k0 + 1) * 256 + n];
        float w10 = src[(size_t)(k0 + 8) * 256 + n];
        float w11 = src[(size_t)(k0 + 9) * 256 + n];

        uint4 f;
        uint32_t l0, l1;
        f.x = split_pack(w00, w01, l0);
        f.y = split_pack(w10, w11, l1);
        f.z = l0;
        f.w = l1;
        g_Wp[z - 2][j] = f;
    } else {
        // values^T fragments: n = d (within-batch), k = v.
        const int lane = j & 31;
        const int ks   = (j >> 5) & 7;       // v block of 16
        const int dblk = (j >> 8) & 63;      // d block of 8
        const int bb   = j >> 14;            // batch
        const int n  = dblk * 8 + (lane >> 2);        // d index
        const int k0 = ks * 16 + (lane & 3) * 2;      // v index

        const float* __restrict__ src = v + ((size_t)bb * 128 + k0) * 512 + n;
        float v00 = src[0];
        float v01 = src[512];
        float v10 = src[8 * 512];
        float v11 = src[9 * 512];

        uint4 f;
        f.x = split_pack_h(v00, v01, f.z);
        f.y = split_pack_h(v10, v11, f.w);
        g_VTp[j] = f;
    }
}

// ---------------------------------------------------------------------------
// Kernel A (R14 version): tensor-core GEMM via mma.sync.
// ---------------------------------------------------------------------------
__global__ __launch_bounds__(256) void gemm_mma_kernel(
    const float* __restrict__ b1, const float* __restrict__ b2)
{
    const int tid  = threadIdx.x;
    const int wid  = tid >> 5;
    const int lane = tid & 31;
    const int g    = lane >> 2;
    const int tg   = lane & 3;

    const int z  = blockIdx.z;
    const int m0 = blockIdx.y * 128;
    const int n0 = blockIdx.x * 64;

    const uint4* __restrict__ Ah = g_Ahp[z];
    const uint4* __restrict__ Al = g_Alp[z];
    const uint4* __restrict__ Bp = g_Wp[z];
    float* __restrict__ C            = z ? g_s2 : g_s1;
    const float* __restrict__ bias   = z ? b2 : b1;

    const int warp_m = wid & 3;
    const int warp_n = wid >> 2;
    const int rb0 = (m0 >> 4) + warp_m * 2;
    const int nb0 = (n0 >> 3) + warp_n * 4;

    float acc[2][4][4];
#pragma unroll
    for (int mt = 0; mt < 2; mt++)
#pragma unroll
        for (int nt = 0; nt < 4; nt++)
#pragma unroll
            for (int c = 0; c < 4; c++) acc[mt][nt][c] = 0.f;

#pragma unroll 2
    for (int ks = 0; ks < 32; ks++) {
        uint4 AH[2], AL[2], Bf[4];
#pragma unroll
        for (int mt = 0; mt < 2; mt++) {
            AH[mt] = Ah[((rb0 + mt) * 32 + ks) * 32 + lane];
            AL[mt] = Al[((rb0 + mt) * 32 + ks) * 32 + lane];
        }
#pragma unroll
        for (int nt = 0; nt < 4; nt++)
            Bf[nt] = Bp[((nb0 + nt) * 32 + ks) * 32 + lane];

#pragma unroll
        for (int mt = 0; mt < 2; mt++)
#pragma unroll
            for (int nt = 0; nt < 4; nt++) {
                mma_bf16(acc[mt][nt], (const uint32_t*)&AH[mt], Bf[nt].x, Bf[nt].y);
                mma_bf16(acc[mt][nt], (const uint32_t*)&AH[mt], Bf[nt].z, Bf[nt].w);
                mma_bf16(acc[mt][nt], (const uint32_t*)&AL[mt], Bf[nt].x, Bf[nt].y);
            }
    }

#pragma unroll
    for (int mt = 0; mt < 2; mt++) {
        const int row = m0 + warp_m * 32 + mt * 16 + g;
#pragma unroll
        for (int nt = 0; nt < 4; nt++) {
            const int col = n0 + warp_n * 32 + nt * 8 + tg * 2;
            const float2 bb = *(const float2*)&bias[col];
            float2 o0, o1;
            o0.x = acc[mt][nt][0] + bb.x;
            o0.y = acc[mt][nt][1] + bb.y;
            o1.x = acc[mt][nt][2] + bb.x;
            o1.y = acc[mt][nt][3] + bb.y;
            *(float2*)&C[(size_t)row * U_ + col]       = o0;
            *(float2*)&C[(size_t)(row + 8) * U_ + col] = o1;
        }
    }
}

// ---------------------------------------------------------------------------
// Kernel B (R13/R14 version): score via tanh.approx.f16x2 feeding mma.sync.
// ---------------------------------------------------------------------------
__global__ __launch_bounds__(256) void score_kernel(
    const float* __restrict__ Vw, const float* __restrict__ Vb)
{
    __shared__ uint32_t sS1[32][132];
    __shared__ uint32_t sS2[32][132];
    __shared__ uint32_t sVw[128];

    const int tid = threadIdx.x;
    const int b   = blockIdx.z;
    const int q0  = blockIdx.y * 32;
    const int v0  = blockIdx.x * 32;

#pragma unroll
    for (int it = 0; it < 8; it++) {
        const int idx = tid + it * 256;
        const int r   = idx >> 6;
        const int c4  = idx & 63;
        float4 x1 = *(const float4*)&g_s1[((b * SQ_) + q0 + r) * U_ + (c4 << 2)];
        sS1[r][2 * c4]     = pack_h2(x1.x, x1.y);
        sS1[r][2 * c4 + 1] = pack_h2(x1.z, x1.w);
        float4 x2 = *(const float4*)&g_s2[((b * SV_) + v0 + r) * U_ + (c4 << 2)];
        sS2[r][2 * c4]     = pack_h2(x2.x, x2.y);
        sS2[r][2 * c4 + 1] = pack_h2(x2.z, x2.w);
    }
    if (tid < 128) sVw[tid] = pack_h2(Vw[2 * tid], Vw[2 * tid + 1]);
    __syncthreads();

    const int wid  = tid >> 5;
    const int lane = tid & 31;
    const int qq = wid * 4;
    const int tr = lane >> 2;
    const int tc = lane & 3;

    float d[8][4];
#pragma unroll
    for (int m = 0; m < 8; m++)
#pragma unroll
        for (int c = 0; c < 4; c++) d[m][c] = 0.f;

#pragma unroll 4
    for (int kc = 0; kc < 16; kc++) {
        const uint32_t bf0 = sVw[kc * 8 + tc];
        const uint32_t bf1 = sVw[kc * 8 + tc + 4];
        const int cp0 = kc * 8 + tc;
        const int cp1 = cp0 + 4;
#pragma unroll
        for (int m = 0; m < 8; m++) {
            const int ql = qq + ((m >> 2) << 1);
            const int vl = ((m & 3) << 3) + tr;
            const uint32_t s2a = sS2[vl][cp0];
            const uint32_t s2b = sS2[vl][cp1];
            const uint32_t s1a = sS1[ql][cp0];
            const uint32_t s1b = sS1[ql + 1][cp0];
            const uint32_t s1c = sS1[ql][cp1];
            const uint32_t s1d = sS1[ql + 1][cp1];

            __half2 h0 = __hadd2(*(const __half2*)&s1a, *(const __half2*)&s2a);
            __half2 h1 = __hadd2(*(const __half2*)&s1b, *(const __half2*)&s2a);
            __half2 h2v = __hadd2(*(const __half2*)&s1c, *(const __half2*)&s2b);
            __half2 h3 = __hadd2(*(const __half2*)&s1d, *(const __half2*)&s2b);

            uint32_t a0, a1, a2, a3;
            asm("tanh.approx.f16x2 %0, %1;" : "=r"(a0) : "r"(*(uint32_t*)&h0));
            asm("tanh.approx.f16x2 %0, %1;" : "=r"(a1) : "r"(*(uint32_t*)&h1));
            asm("tanh.approx.f16x2 %0, %1;" : "=r"(a2) : "r"(*(uint32_t*)&h2v));
            asm("tanh.approx.f16x2 %0, %1;" : "=r"(a3) : "r"(*(uint32_t*)&h3));

            mma_f16(d[m], a0, a1, a2, a3, bf0, bf1);
        }
    }

    const float vb = Vb[0];
    if (tc == 0) {
#pragma unroll
        for (int m = 0; m < 8; m++) {
            const int ql = qq + ((m >> 2) << 1);
            const int vl = ((m & 3) << 3) + tr;
            g_score[((b * SQ_) + q0 + ql) * SV_ + v0 + vl]     = d[m][0] + vb;
            g_score[((b * SQ_) + q0 + ql + 1) * SV_ + v0 + vl] = d[m][2] + vb;
        }
    }
}

// ---------------------------------------------------------------------------
// Kernel C: fused softmax + context GEMM; B tile prefetched to smem via
// cp.async AT KERNEL ENTRY so its L2 latency hides behind the softmax phase.
// Dynamic smem layout:
//   [0, 64K)      sB   : 4096 uint4  (whole B slab for this (b, dtile))
//   [64K, 80K)    sW   : float[32][128]
//   [80K, +8.5K)  sWh  : uint32[32][66]
//   [88.5K,+8.5K) sWl  : uint32[32][66]
// ---------------------------------------------------------------------------
#define CTX_SB_    0
#define CTX_SW_    65536
#define CTX_SWH_   (65536 + 16384)
#define CTX_SWL_   (CTX_SWH_ + 32 * 66 * 4)
#define CTX_SMEM_  (CTX_SWL_ + 32 * 66 * 4)

__global__ __launch_bounds__(256) void ctx_kernel(
    float* __restrict__ out_w,
    float* __restrict__ out_ctx)
{
    extern __shared__ char smem[];
    const uint32_t smb = smem_u32(smem);
    const uint4* sB  = (const uint4*)(smem + CTX_SB_);
    float (*sW)[128]  = (float(*)[128])(smem + CTX_SW_);
    uint32_t (*sWh)[66] = (uint32_t(*)[66])(smem + CTX_SWH_);
    uint32_t (*sWl)[66] = (uint32_t(*)[66])(smem + CTX_SWL_);

    const int tid = threadIdx.x;
    const int b   = blockIdx.z;
    const int q0  = blockIdx.y * 32;
    const int dt  = blockIdx.x;        // d tile: d0 = dt*128

    // Phase 0: prefetch the whole contiguous B slab (64 KB) for this tile.
    {
        const uint4* gsrc = g_VTp + (((size_t)b * 64 + (size_t)dt * 16) * 8) * 32;
#pragma unroll
        for (int it = 0; it < 16; it++) {
            const int idx = tid + it * 256;        // 0..4095
            cp_async16(smb + CTX_SB_ + (uint32_t)idx * 16, gsrc + idx);
        }
        CP_COMMIT();
    }

    // Phase 1: load score tile + row softmax (fp32) — overlaps the cp.async.
#pragma unroll
    for (int k = 0; k < 4; k++) {
        const int idx = tid + k * 256;
        const int r   = idx >> 5;
        const int c4  = idx & 31;
        float4 s = *(const float4*)&g_score[((b * SQ_) + q0 + r) * SV_ + (c4 << 2)];
        *(float4*)&sW[r][c4 << 2] = s;
    }
    __syncthreads();

    const int warp = tid >> 5;
    const int lane = tid & 31;
#pragma unroll
    for (int i = 0; i < 4; i++) {
        const int r = warp * 4 + i;
        float sc[4];
#pragma unroll
        for (int j = 0; j < 4; j++) sc[j] = sW[r][lane + 32 * j];
        float m = fmaxf(fmaxf(sc[0], sc[1]), fmaxf(sc[2], sc[3]));
#pragma unroll
        for (int o = 16; o > 0; o >>= 1)
            m = fmaxf(m, __shfl_xor_sync(0xFFFFFFFFu, m, o));
        float e[4], s = 0.f;
#pragma unroll
        for (int j = 0; j < 4; j++) { e[j] = __expf(sc[j] - m); s += e[j]; }
#pragma unroll
        for (int o = 16; o > 0; o >>= 1)
            s += __shfl_xor_sync(0xFFFFFFFFu, s, o);
        float inv = __fdividef(1.f, s);
#pragma unroll
        for (int j = 0; j < 4; j++) {
            float w = e[j] * inv;
            sW[r][lane + 32 * j] = w;
            if (dt == 0)
                out_w[((b * SQ_) + q0 + r) * SV_ + lane + 32 * j] = w;
        }
    }
    __syncthreads();

    // Pack w -> f16 hi/lo pair arrays (8 pairs per thread).
    {
        const int row = tid >> 3;
        const int p0  = (tid & 7) * 8;
#pragma unroll
        for (int p = 0; p < 8; p++) {
            const int pp = p0 + p;
            uint32_t l;
            sWh[row][pp] = split_pack_h(sW[row][2 * pp], sW[row][2 * pp + 1], l);
            sWl[row][pp] = l;
        }
    }
    CP_WAIT0();
    __syncthreads();

    // Phase 2: context GEMM from smem. Warp -> (mt = wid&1, ng = wid>>1).
    const int tr = lane >> 2;
    const int tc = lane & 3;
    const int mt = warp & 1;
    const int ng = warp >> 1;
    const int r0 = mt * 16 + tr;

    float acc[4][4];
#pragma unroll
    for (int i = 0; i < 4; i++)
#pragma unroll
        for (int c = 0; c < 4; c++) acc[i][c] = 0.f;

#pragma unroll
    for (int k = 0; k < 8; k++) {
        const int cp = k * 8 + tc;
        const uint32_t ah0 = sWh[r0][cp];
        const uint32_t ah1 = sWh[r0 + 8][cp];
        const uint32_t ah2 = sWh[r0][cp + 4];
        const uint32_t ah3 = sWh[r0 + 8][cp + 4];
        const uint32_t al0 = sWl[r0][cp];
        const uint32_t al1 = sWl[r0 + 8][cp];
        const uint32_t al2 = sWl[r0][cp + 4];
        const uint32_t al3 = sWl[r0 + 8][cp + 4];
#pragma unroll
        for (int i = 0; i < 4; i++) {
            const int dblk = ng * 4 + i;          // local d-block (of 16)
            uint4 Bf = sB[((size_t)dblk * 8 + k) * 32 + lane];
            mma_f16(acc[i], ah0, ah1, ah2, ah3, Bf.x, Bf.y);   // wh * vh
            mma_f16(acc[i], ah0, ah1, ah2, ah3, Bf.z, Bf.w);   // wh * vl
            mma_f16(acc[i], al0, al1, al2, al3, Bf.x, Bf.y);   // wl * vh
        }
    }

#pragma unroll
    for (int i = 0; i < 4; i++) {
        const int d  = dt * 128 + (ng * 4 + i) * 8 + tc * 2;
        const int qa = q0 + r0;
        float2 o0, o1;
        o0.x = acc[i][0]; o0.y = acc[i][1];
        o1.x = acc[i][2]; o1.y = acc[i][3];
        *(float2*)&out_ctx[((size_t)(b * SQ_) + qa) * DV_ + d]     = o0;
        *(float2*)&out_ctx[((size_t)(b * SQ_) + qa + 8) * DV_ + d] = o1;
    }
}

// ---------------------------------------------------------------------------
extern "C" void kernel_launch(void* const* d_in, const int* in_sizes, int n_in,
                              void* d_out, int out_size)
{
    const float* query  = (const float*)d_in[0];
    const float* values = (const float*)d_in[1];
    const float* W1     = (const float*)d_in[2];
    const float* b1     = (const float*)d_in[3];
    const float* W2     = (const float*)d_in[4];
    const float* b2     = (const float*)d_in[5];
    const float* Vw     = (const float*)d_in[6];
    const float* Vb     = (const float*)d_in[7];

    float* out_ctx = (float*)d_out;                      // [16,128,512]
    float* out_w   = out_ctx + B_ * SQ_ * DV_;           // [16,128,128,1]

    // fp32 -> packed fragment layouts (A/B for gemm, values^T for ctx)
    convert_kernel<<<dim3(1024, 5), 256>>>(query, values, W1, W2);

    // tensor-core GEMMs: s1 = q@W1+b1, s2 = v@W2+b2
    gemm_mma_kernel<<<dim3(4, 16, 2), 256>>>(b1, b2);

    // score = reduce_u tanh(s1+s2)*Vw + Vb  (tanh.f16x2 -> mma.sync)
    score_kernel<<<dim3(SV_ / 32, SQ_ / 32, B_), 256>>>(Vw, Vb);

    // fused softmax + context GEMM (B slab prefetched to smem)
    cudaFuncSetAttribute(ctx_kernel,
                         cudaFuncAttributeMaxDynamicSharedMemorySize, CTX_SMEM_);
    ctx_kernel<<<dim3(4, 4, 16), 256, CTX_SMEM_>>>(out_w, out_ctx);
}